// round 2
// baseline (speedup 1.0000x reference)
#include <cuda_runtime.h>
#include <cstdint>

#define IC    1024   // input capsules
#define CDIM  256    // input dim
#define NC    16     // num output capsules
#define DD    32     // capsule dim
#define CH    32     // i-chunk rows staged in smem
#define NCHUNK (IC / CH)
#define THREADS 512
#define KSPLIT 16            // step-A k groups (== warps)
#define CPK (CDIM / KSPLIT)  // 16 channels per k-group
#define EPS 1e-7f

// ---- smem layout (float offsets) ----
#define OFF_U     0                       // 2 * 32 * 256 = 16384 (double buffered, xor-swizzled)
#define OFF_W     16384                   // 16*256 = 4096
#define OFF_VPART 20480                   // 4 * 16*256 = 16384
#define OFF_BLOG  36864                   // 16 * 16 * 33 = 8448
#define OFF_CS    45312                   // 16 * 33 = 528
#define OFF_OUT   45840                   // 16*32 = 512
#define OFF_USUM  46352                   // 256
#define SMEM_FLOATS 46608
#define SMEM_BYTES (SMEM_FLOATS * 4)

// xor swizzle at float4 granularity: row-major 32x256 tile, conflict-limited
// for both row-broadcast (step A) and strided-column (step C) reads.
__device__ __forceinline__ int uswz(int row, int c) {
    return row * CDIM + ((((c >> 2) ^ (row & 15)) << 2) | (c & 3));
}

__device__ __forceinline__ void prefetch_chunk(float* sm, const float* u, int chunk, int buf, int t) {
    const float* src = u + (size_t)chunk * CH * CDIM;
#pragma unroll
    for (int k = 0; k < 4; k++) {
        int idx = t + k * THREADS;        // 0..2047 (32 rows * 64 float4)
        int row = idx >> 6;
        int c4  = idx & 63;
        float* dstp = &sm[OFF_U + buf * (CH * CDIM) + row * CDIM + ((c4 ^ (row & 15)) << 2)];
        unsigned dst = (unsigned)__cvta_generic_to_shared(dstp);
        const float* g = src + row * CDIM + c4 * 4;
        asm volatile("cp.async.cg.shared.global [%0], [%1], 16;" :: "r"(dst), "l"(g));
    }
    asm volatile("cp.async.commit_group;");
}

// Per-warp (warp == capsule n): s[n] = scale * (vsrc . W_n), squash -> out.
// If gout != nullptr: write final output and return. Else write out_s and w_s[n][c] = W_n @ out.
__device__ __forceinline__ void boundary(float* sm, const float* vsrc_base, int per_n_stride,
                                         float scale, const float* __restrict__ W,
                                         bool write_w, float* gout, int wid, int lane) {
    const float* vsrc = vsrc_base + wid * per_n_stride;
    const float* Wp = W + wid * DD + lane;       // W[c*512 + n*32 + d]
    float s = 0.f;
#pragma unroll 8
    for (int c = 0; c < CDIM; c++) s += vsrc[c] * Wp[c * (NC * DD)];
    s *= scale;
    float ss = s * s;
#pragma unroll
    for (int o = 16; o > 0; o >>= 1) ss += __shfl_xor_sync(0xffffffffu, ss, o);
    float ov = s * rsqrtf(ss + EPS);
    if (gout) { gout[wid * DD + lane] = ov; return; }
    sm[OFF_OUT + wid * DD + lane] = ov;
    __syncwarp();
    if (write_w) {
#pragma unroll
        for (int k = 0; k < 8; k++) {
            int c = lane + 32 * k;
            const float* Wc = W + c * (NC * DD) + wid * DD;
            float a = 0.f;
#pragma unroll
            for (int dd = 0; dd < DD; dd += 4) {
                float4 w4 = *(const float4*)(Wc + dd);
                a += w4.x * sm[OFF_OUT + wid * DD + dd + 0];
                a += w4.y * sm[OFF_OUT + wid * DD + dd + 1];
                a += w4.z * sm[OFF_OUT + wid * DD + dd + 2];
                a += w4.w * sm[OFF_OUT + wid * DD + dd + 3];
            }
            sm[OFF_W + wid * CDIM + c] = a;
        }
    }
}

__global__ __launch_bounds__(THREADS, 1)
void caps_route_kernel(const float* __restrict__ u_vecs, const float* __restrict__ W,
                       float* __restrict__ gout) {
    extern __shared__ float sm[];
    const int t = threadIdx.x, wid = t >> 5, lane = t & 31;
    const int b = blockIdx.x;
    const float* u = u_vecs + (size_t)b * IC * CDIM;

    // ---------- pass 0: usum[c] = sum_i u[i][c]; out0 = squash(usum/16 @ W_n) ----------
    {
        int c = t & 255, half = t >> 8;
        const float* up = u + (size_t)half * (IC / 2) * CDIM + c;
        float a = 0.f;
#pragma unroll 8
        for (int i = 0; i < IC / 2; i++) a += up[(size_t)i * CDIM];
        sm[OFF_BLOG + half * 256 + c] = a;   // scratch
    }
    __syncthreads();
    if (t < 256) sm[OFF_USUM + t] = sm[OFF_BLOG + t] + sm[OFF_BLOG + 256 + t];
    __syncthreads();
    boundary(sm, &sm[OFF_USUM], 0, 1.f / 16.f, W, true, nullptr, wid, lane);
    __syncthreads();

    // ---------- 2 fused routing passes ----------
    for (int pass = 0; pass < 2; ++pass) {
        float vacc[4][8];
#pragma unroll
        for (int m = 0; m < 4; m++)
#pragma unroll
            for (int j = 0; j < 8; j++) vacc[m][j] = 0.f;

        prefetch_chunk(sm, u, 0, 0, t);

        for (int chunk = 0; chunk < NCHUNK; ++chunk) {
            int buf = chunk & 1;
            asm volatile("cp.async.wait_group 0;" ::: "memory");
            __syncthreads();
            if (chunk + 1 < NCHUNK) prefetch_chunk(sm, u, chunk + 1, buf ^ 1, t);
            const float* ub = &sm[OFF_U + buf * (CH * CDIM)];

            // --- step A: blog[n][ii] = w[n] . u[ii], k-split over warps ---
            {
                const int kg = wid;
                const int cb = kg * CPK;
                float acc[NC];
#pragma unroll
                for (int n = 0; n < NC; n++) acc[n] = 0.f;
#pragma unroll
                for (int c4 = 0; c4 < CPK; c4 += 4) {
                    int cbase = cb + c4;
                    float u0 = ub[uswz(lane, cbase + 0)];
                    float u1 = ub[uswz(lane, cbase + 1)];
                    float u2 = ub[uswz(lane, cbase + 2)];
                    float u3 = ub[uswz(lane, cbase + 3)];
#pragma unroll
                    for (int n = 0; n < NC; n++) {
                        float4 w4 = *(const float4*)&sm[OFF_W + n * CDIM + cbase];
                        acc[n] += u0 * w4.x;
                        acc[n] += u1 * w4.y;
                        acc[n] += u2 * w4.z;
                        acc[n] += u3 * w4.w;
                    }
                }
#pragma unroll
                for (int n = 0; n < NC; n++)
                    sm[OFF_BLOG + kg * (NC * 33) + n * 33 + lane] = acc[n];
            }
            __syncthreads();

            // --- softmax over n (per ii): reduce k-partials then width-16 shuffles ---
            {
                int ii = t >> 4, n = t & 15;
                float bl = 0.f;
#pragma unroll
                for (int kg = 0; kg < KSPLIT; kg++)
                    bl += sm[OFF_BLOG + kg * (NC * 33) + n * 33 + ii];
                float m = bl;
#pragma unroll
                for (int o = 8; o > 0; o >>= 1) m = fmaxf(m, __shfl_xor_sync(0xffffffffu, m, o, 16));
                float e = __expf(bl - m);
                float ssum = e;
#pragma unroll
                for (int o = 8; o > 0; o >>= 1) ssum += __shfl_xor_sync(0xffffffffu, ssum, o, 16);
                sm[OFF_CS + n * 33 + ii] = e / ssum;
            }
            __syncthreads();

            // --- step C: v[n][c] += c[n][ii] * u[ii][c]  (4 n x 8 ch per thread, regs) ---
            {
                const int ngrp = wid >> 2, isub = wid & 3, n0 = ngrp * 4;
#pragma unroll
                for (int k = 0; k < 8; k++) {
                    int ii = isub * 8 + k;
                    float c0 = sm[OFF_CS + (n0 + 0) * 33 + ii];
                    float c1 = sm[OFF_CS + (n0 + 1) * 33 + ii];
                    float c2 = sm[OFF_CS + (n0 + 2) * 33 + ii];
                    float c3 = sm[OFF_CS + (n0 + 3) * 33 + ii];
#pragma unroll
                    for (int j = 0; j < 8; j++) {
                        float uu = ub[uswz(ii, lane + 32 * j)];
                        vacc[0][j] += c0 * uu;
                        vacc[1][j] += c1 * uu;
                        vacc[2][j] += c2 * uu;
                        vacc[3][j] += c3 * uu;
                    }
                }
            }
            // loop-top wait+sync protects all cross-chunk hazards
        }

        // dump register v partials, reduce the 4 ii-split copies
        {
            const int ngrp = wid >> 2, isub = wid & 3, n0 = ngrp * 4;
#pragma unroll
            for (int m = 0; m < 4; m++)
#pragma unroll
                for (int j = 0; j < 8; j++)
                    sm[OFF_VPART + isub * (NC * CDIM) + (n0 + m) * CDIM + lane + 32 * j] = vacc[m][j];
        }
        __syncthreads();
        for (int idx = t; idx < NC * CDIM; idx += THREADS) {
            sm[OFF_VPART + idx] = sm[OFF_VPART + idx]
                                + sm[OFF_VPART + 1 * NC * CDIM + idx]
                                + sm[OFF_VPART + 2 * NC * CDIM + idx]
                                + sm[OFF_VPART + 3 * NC * CDIM + idx];
        }
        __syncthreads();

        bool last = (pass == 1);
        boundary(sm, &sm[OFF_VPART], CDIM, 1.f, W, !last,
                 last ? (gout + (size_t)b * NC * DD) : nullptr, wid, lane);
        __syncthreads();
    }
}

extern "C" void kernel_launch(void* const* d_in, const int* in_sizes, int n_in,
                              void* d_out, int out_size) {
    const float* u_vecs = (const float*)d_in[0];   // (128, 1024, 256) fp32
    const float* W      = (const float*)d_in[1];   // (256, 512) fp32
    float* out          = (float*)d_out;           // (128, 16, 32) fp32

    cudaFuncSetAttribute(caps_route_kernel, cudaFuncAttributeMaxDynamicSharedMemorySize, SMEM_BYTES);
    caps_route_kernel<<<128, THREADS, SMEM_BYTES>>>(u_vecs, W, out);
}

// round 3
// speedup vs baseline: 1.0644x; 1.0644x over previous
#include <cuda_runtime.h>
#include <cstdint>

#define IC    1024   // input capsules
#define CDIM  256    // input dim
#define NC    16     // num output capsules
#define DD    32     // capsule dim
#define CH    32     // i-chunk rows staged in smem
#define NCHUNK (IC / CH)
#define THREADS 512
#define STAGES 4
#define KSPLIT 16            // step-A k groups (== warps)
#define CPK (CDIM / KSPLIT)  // 16 channels per k-group
#define EPS 1e-7f

// ---- smem layout (float offsets) ----
#define OFF_U     0                       // STAGES * 32*256 = 32768 floats (ring, xor-swizzled)
#define OFF_VPART 0                       // aliases U ring: only live after chunk loop (16384 fl)
#define OFF_W     32768                   // 16*256 = 4096
#define OFF_BLOG  36864                   // 16 * 16 * 33 = 8448 (also pass-0 scratch)
#define OFF_CS    45312                   // 16 * 33 = 528
#define OFF_OUT   45840                   // 16*32 = 512
#define OFF_USUM  46352                   // 256
#define SMEM_FLOATS 46608
#define SMEM_BYTES (SMEM_FLOATS * 4)

// ---- packed f32x2 helpers (sm_100+) ----
__device__ __forceinline__ unsigned long long ffma2(unsigned long long a, unsigned long long b,
                                                    unsigned long long c) {
    unsigned long long d;
    asm("fma.rn.f32x2 %0, %1, %2, %3;" : "=l"(d) : "l"(a), "l"(b), "l"(c));
    return d;
}
__device__ __forceinline__ unsigned long long pk2(float v) {
    unsigned long long d; asm("mov.b64 %0, {%1, %1};" : "=l"(d) : "f"(v)); return d;
}
__device__ __forceinline__ float2 upk(unsigned long long d) {
    float2 r; asm("mov.b64 {%0, %1}, %2;" : "=f"(r.x), "=f"(r.y) : "l"(d)); return r;
}

__device__ __forceinline__ void prefetch_chunk(float* sm, const float* u, int chunk, int buf, int t) {
    const float* src = u + (size_t)chunk * CH * CDIM;
#pragma unroll
    for (int k = 0; k < 4; k++) {
        int idx = t + k * THREADS;        // 0..2047 (32 rows * 64 float4)
        int row = idx >> 6;
        int c4  = idx & 63;
        float* dstp = &sm[OFF_U + buf * (CH * CDIM) + row * CDIM + ((c4 ^ (row & 15)) << 2)];
        unsigned dst = (unsigned)__cvta_generic_to_shared(dstp);
        const float* g = src + row * CDIM + c4 * 4;
        asm volatile("cp.async.cg.shared.global [%0], [%1], 16;" :: "r"(dst), "l"(g));
    }
    asm volatile("cp.async.commit_group;");
}

// Per-warp (warp == capsule n): s[n] = scale * (vsrc . W_n), squash -> out.
// If gout != nullptr: write final output and return. Else write out_s and w_s[n][c] = W_n @ out.
__device__ __forceinline__ void boundary(float* sm, const float* vsrc_base, int per_n_stride,
                                         float scale, const float* __restrict__ W,
                                         bool write_w, float* gout, int wid, int lane) {
    const float* vsrc = vsrc_base + wid * per_n_stride;
    const float* Wp = W + wid * DD + lane;       // W[c*512 + n*32 + d]
    float s = 0.f;
#pragma unroll 8
    for (int c = 0; c < CDIM; c++) s += vsrc[c] * Wp[c * (NC * DD)];
    s *= scale;
    float ss = s * s;
#pragma unroll
    for (int o = 16; o > 0; o >>= 1) ss += __shfl_xor_sync(0xffffffffu, ss, o);
    float ov = s * rsqrtf(ss + EPS);
    if (gout) { gout[wid * DD + lane] = ov; return; }
    sm[OFF_OUT + wid * DD + lane] = ov;
    __syncwarp();
    if (write_w) {
#pragma unroll
        for (int k = 0; k < 8; k++) {
            int c = lane + 32 * k;
            const float* Wc = W + c * (NC * DD) + wid * DD;
            float a = 0.f;
#pragma unroll
            for (int dd = 0; dd < DD; dd += 4) {
                float4 w4 = *(const float4*)(Wc + dd);
                a += w4.x * sm[OFF_OUT + wid * DD + dd + 0];
                a += w4.y * sm[OFF_OUT + wid * DD + dd + 1];
                a += w4.z * sm[OFF_OUT + wid * DD + dd + 2];
                a += w4.w * sm[OFF_OUT + wid * DD + dd + 3];
            }
            sm[OFF_W + wid * CDIM + c] = a;
        }
    }
}

__global__ __launch_bounds__(THREADS, 1)
void caps_route_kernel(const float* __restrict__ u_vecs, const float* __restrict__ W,
                       float* __restrict__ gout) {
    extern __shared__ float sm[];
    const int t = threadIdx.x, wid = t >> 5, lane = t & 31;
    const int b = blockIdx.x;
    const float* u = u_vecs + (size_t)b * IC * CDIM;

    // ---------- pass 0: usum[c] = sum_i u[i][c]; out0 = squash(usum/16 @ W_n) ----------
    {
        int c4 = t & 63, rg = t >> 6;     // 8 row groups x 64 quads
        const float* up = u + (size_t)rg * CDIM + c4 * 4;
        float4 a = make_float4(0.f, 0.f, 0.f, 0.f);
#pragma unroll 8
        for (int i = 0; i < IC / 8; i++) {
            float4 v = *(const float4*)(up + (size_t)i * 8 * CDIM);
            a.x += v.x; a.y += v.y; a.z += v.z; a.w += v.w;
        }
        *(float4*)&sm[OFF_BLOG + rg * CDIM + c4 * 4] = a;
    }
    __syncthreads();
    if (t < 256) {
        float a = 0.f;
#pragma unroll
        for (int rg = 0; rg < 8; rg++) a += sm[OFF_BLOG + rg * CDIM + t];
        sm[OFF_USUM + t] = a;
    }
    __syncthreads();
    boundary(sm, &sm[OFF_USUM], 0, 1.f / 16.f, W, true, nullptr, wid, lane);
    __syncthreads();

    // ---------- 2 fused routing passes ----------
    for (int pass = 0; pass < 2; ++pass) {
        unsigned long long vac2[4][4];     // 4 capsules x 4 channel-pairs (8 channels)
#pragma unroll
        for (int m = 0; m < 4; m++)
#pragma unroll
            for (int j = 0; j < 4; j++) vac2[m][j] = 0ull;

        prefetch_chunk(sm, u, 0, 0, t);
        prefetch_chunk(sm, u, 1, 1, t);
        prefetch_chunk(sm, u, 2, 2, t);

        for (int chunk = 0; chunk < NCHUNK; ++chunk) {
            if (chunk <= NCHUNK - 3)      asm volatile("cp.async.wait_group 2;" ::: "memory");
            else if (chunk == NCHUNK - 2) asm volatile("cp.async.wait_group 1;" ::: "memory");
            else                          asm volatile("cp.async.wait_group 0;" ::: "memory");
            __syncthreads();
            if (chunk + STAGES - 1 < NCHUNK)
                prefetch_chunk(sm, u, chunk + STAGES - 1, (chunk + STAGES - 1) & (STAGES - 1), t);
            const float* ub = &sm[OFF_U + (chunk & (STAGES - 1)) * (CH * CDIM)];

            // --- step A: blog[n][row] = w[n] . u[row], k-split over warps, f32x2 ---
            {
                const int kg = wid;
                const int row = lane, s = row & 15;
                const float* rb = ub + row * CDIM;
                ulonglong2 uq[4];
#pragma unroll
                for (int j = 0; j < 4; j++)
                    uq[j] = *(const ulonglong2*)(rb + (((kg * 4 + j) ^ s) << 2));
#pragma unroll
                for (int n = 0; n < NC; n++) {
                    const float* wb = &sm[OFF_W + n * CDIM + kg * CPK];
                    unsigned long long acc = 0ull;
#pragma unroll
                    for (int j = 0; j < 4; j++) {
                        ulonglong2 w2 = *(const ulonglong2*)(wb + 4 * j);
                        acc = ffma2(uq[j].x, w2.x, acc);
                        acc = ffma2(uq[j].y, w2.y, acc);
                    }
                    float2 f = upk(acc);
                    sm[OFF_BLOG + kg * (NC * 33) + n * 33 + row] = f.x + f.y;
                }
            }
            __syncthreads();

            // --- softmax over n (per row ii): reduce k-partials then width-16 shuffles ---
            {
                int ii = t >> 4, n = t & 15;
                float bl = 0.f;
#pragma unroll
                for (int kg = 0; kg < KSPLIT; kg++)
                    bl += sm[OFF_BLOG + kg * (NC * 33) + n * 33 + ii];
                float m = bl;
#pragma unroll
                for (int o = 8; o > 0; o >>= 1) m = fmaxf(m, __shfl_xor_sync(0xffffffffu, m, o, 16));
                float e = __expf(bl - m);
                float ssum = e;
#pragma unroll
                for (int o = 8; o > 0; o >>= 1) ssum += __shfl_xor_sync(0xffffffffu, ssum, o, 16);
                sm[OFF_CS + n * 33 + ii] = e / ssum;
            }
            __syncthreads();

            // --- step C: v[n][c] += c[n][ii] * u[ii][c]; lane owns 8 consecutive ch ---
            {
                const int ngrp = wid >> 2, isub = wid & 3, n0 = ngrp * 4;
#pragma unroll
                for (int k = 0; k < 8; k++) {
                    int ii = isub * 8 + k, s = ii & 15;
                    const float* rb = ub + ii * CDIM;
                    ulonglong2 ua = *(const ulonglong2*)(rb + (((lane * 2 + 0) ^ s) << 2));
                    ulonglong2 ubp = *(const ulonglong2*)(rb + (((lane * 2 + 1) ^ s) << 2));
#pragma unroll
                    for (int m = 0; m < 4; m++) {
                        unsigned long long cc = pk2(sm[OFF_CS + (n0 + m) * 33 + ii]);
                        vac2[m][0] = ffma2(ua.x,  cc, vac2[m][0]);
                        vac2[m][1] = ffma2(ua.y,  cc, vac2[m][1]);
                        vac2[m][2] = ffma2(ubp.x, cc, vac2[m][2]);
                        vac2[m][3] = ffma2(ubp.y, cc, vac2[m][3]);
                    }
                }
            }
        }
        __syncthreads();   // U ring dead; VPART (alias) becomes live

        // dump register v partials (pairs -> STS.64), reduce the 4 ii-split copies
        {
            const int ngrp = wid >> 2, isub = wid & 3, n0 = ngrp * 4;
#pragma unroll
            for (int m = 0; m < 4; m++)
#pragma unroll
                for (int p = 0; p < 4; p++)
                    *(unsigned long long*)&sm[OFF_VPART + isub * (NC * CDIM)
                                              + (n0 + m) * CDIM + lane * 8 + p * 2] = vac2[m][p];
        }
        __syncthreads();
        for (int q = t; q < (NC * CDIM) / 4; q += THREADS) {
            float4 a = *(float4*)&sm[OFF_VPART + 4 * q];
            float4 b1 = *(float4*)&sm[OFF_VPART + 1 * NC * CDIM + 4 * q];
            float4 b2 = *(float4*)&sm[OFF_VPART + 2 * NC * CDIM + 4 * q];
            float4 b3 = *(float4*)&sm[OFF_VPART + 3 * NC * CDIM + 4 * q];
            a.x += b1.x + b2.x + b3.x;
            a.y += b1.y + b2.y + b3.y;
            a.z += b1.z + b2.z + b3.z;
            a.w += b1.w + b2.w + b3.w;
            *(float4*)&sm[OFF_VPART + 4 * q] = a;
        }
        __syncthreads();

        bool last = (pass == 1);
        boundary(sm, &sm[OFF_VPART], CDIM, 1.f, W, !last,
                 last ? (gout + (size_t)b * NC * DD) : nullptr, wid, lane);
        __syncthreads();   // protects next pass's prefetch into aliased U ring
    }
}

extern "C" void kernel_launch(void* const* d_in, const int* in_sizes, int n_in,
                              void* d_out, int out_size) {
    const float* u_vecs = (const float*)d_in[0];   // (128, 1024, 256) fp32
    const float* W      = (const float*)d_in[1];   // (256, 512) fp32
    float* out          = (float*)d_out;           // (128, 16, 32) fp32

    cudaFuncSetAttribute(caps_route_kernel, cudaFuncAttributeMaxDynamicSharedMemorySize, SMEM_BYTES);
    caps_route_kernel<<<128, THREADS, SMEM_BYTES>>>(u_vecs, W, out);
}

// round 4
// speedup vs baseline: 1.2296x; 1.1551x over previous
#include <cuda_runtime.h>
#include <cstdint>

#define IC    1024   // input capsules
#define CDIM  256    // input dim
#define NC    16     // num output capsules
#define DD    32     // capsule dim
#define CH    64     // i-chunk rows staged in smem
#define NCHUNK (IC / CH)
#define THREADS 512
#define EPS 1e-7f

// ---- smem layout (float offsets) ----
#define OFF_U     0                       // 2 * 64*256 = 32768 floats (double buffer, xor-swizzled)
#define OFF_VPART 0                       // aliases U ring: only live after chunk loop (16384 fl)
#define OFF_W     32768                   // 16*256 = 4096
#define OFF_BLOG  36864                   // 16 kg * 16 n * 65 = 16640 (also pass-0 scratch)
#define OFF_CS    53504                   // 64 rows * 16 n = 1024 (transposed [row][n])
#define OFF_OUT   54528                   // 16*32 = 512
#define OFF_USUM  55040                   // 256
#define SMEM_FLOATS 55296
#define SMEM_BYTES (SMEM_FLOATS * 4)      // 221184 B

// ---- packed f32x2 helpers (sm_100+) ----
__device__ __forceinline__ unsigned long long ffma2(unsigned long long a, unsigned long long b,
                                                    unsigned long long c) {
    unsigned long long d;
    asm("fma.rn.f32x2 %0, %1, %2, %3;" : "=l"(d) : "l"(a), "l"(b), "l"(c));
    return d;
}
__device__ __forceinline__ unsigned long long pk2(float v) {
    unsigned long long d; asm("mov.b64 %0, {%1, %1};" : "=l"(d) : "f"(v)); return d;
}
__device__ __forceinline__ float2 upk(unsigned long long d) {
    float2 r; asm("mov.b64 {%0, %1}, %2;" : "=f"(r.x), "=f"(r.y) : "l"(d)); return r;
}

__device__ __forceinline__ void prefetch_chunk(float* sm, const float* u, int chunk, int buf, int t) {
    const float* src = u + (size_t)chunk * CH * CDIM;
#pragma unroll
    for (int k = 0; k < 8; k++) {
        int idx = t + k * THREADS;        // 0..4095 (64 rows * 64 float4)
        int row = idx >> 6;
        int c4  = idx & 63;
        float* dstp = &sm[OFF_U + buf * (CH * CDIM) + row * CDIM + ((c4 ^ (row & 15)) << 2)];
        unsigned dst = (unsigned)__cvta_generic_to_shared(dstp);
        const float* g = src + row * CDIM + c4 * 4;
        asm volatile("cp.async.cg.shared.global [%0], [%1], 16;" :: "r"(dst), "l"(g));
    }
    asm volatile("cp.async.commit_group;");
}

// Per-warp (warp == capsule n): s[n] = scale * (vsrc . W_n), squash -> out.
// If gout != nullptr: write final output and return. Else write out_s and w_s[n][c] = W_n @ out.
__device__ __forceinline__ void boundary(float* sm, const float* vsrc_base, int per_n_stride,
                                         float scale, const float* __restrict__ W,
                                         bool write_w, float* gout, int wid, int lane) {
    const float* vsrc = vsrc_base + wid * per_n_stride;
    const float* Wp = W + wid * DD + lane;       // W[c*512 + n*32 + d]
    float s = 0.f;
#pragma unroll 8
    for (int c = 0; c < CDIM; c++) s += vsrc[c] * Wp[c * (NC * DD)];
    s *= scale;
    float ss = s * s;
#pragma unroll
    for (int o = 16; o > 0; o >>= 1) ss += __shfl_xor_sync(0xffffffffu, ss, o);
    float ov = s * rsqrtf(ss + EPS);
    if (gout) { gout[wid * DD + lane] = ov; return; }
    sm[OFF_OUT + wid * DD + lane] = ov;
    __syncwarp();
    if (write_w) {
#pragma unroll
        for (int k = 0; k < 8; k++) {
            int c = lane + 32 * k;
            const float* Wc = W + c * (NC * DD) + wid * DD;
            float a = 0.f;
#pragma unroll
            for (int dd = 0; dd < DD; dd += 4) {
                float4 w4 = *(const float4*)(Wc + dd);
                a += w4.x * sm[OFF_OUT + wid * DD + dd + 0];
                a += w4.y * sm[OFF_OUT + wid * DD + dd + 1];
                a += w4.z * sm[OFF_OUT + wid * DD + dd + 2];
                a += w4.w * sm[OFF_OUT + wid * DD + dd + 3];
            }
            sm[OFF_W + wid * CDIM + c] = a;
        }
    }
}

__global__ __launch_bounds__(THREADS, 1)
void caps_route_kernel(const float* __restrict__ u_vecs, const float* __restrict__ W,
                       float* __restrict__ gout) {
    extern __shared__ float sm[];
    const int t = threadIdx.x, wid = t >> 5, lane = t & 31;
    const int b = blockIdx.x;
    const float* u = u_vecs + (size_t)b * IC * CDIM;

    // C-step role constants: warp = (nh, chh, rgrp); lane = ch-quad within half
    const int c_nh   = wid & 1;            // n half: n in nh*8..+8
    const int c_chh  = (wid >> 1) & 1;     // channel half
    const int c_rgrp = wid >> 2;           // row group of 16 (0..3)
    const int c_Q    = c_chh * 32 + lane;  // channel quad 0..63

    // ---------- pass 0: usum[c] = sum_i u[i][c]; out0 = squash(usum/16 @ W_n) ----------
    {
        int c4 = t & 63, rg = t >> 6;     // 8 row groups x 64 quads
        const float* up = u + (size_t)rg * CDIM + c4 * 4;
        float4 a = make_float4(0.f, 0.f, 0.f, 0.f);
#pragma unroll 8
        for (int i = 0; i < IC / 8; i++) {
            float4 v = *(const float4*)(up + (size_t)i * 8 * CDIM);
            a.x += v.x; a.y += v.y; a.z += v.z; a.w += v.w;
        }
        *(float4*)&sm[OFF_BLOG + rg * CDIM + c4 * 4] = a;
    }
    __syncthreads();
    if (t < 256) {
        float a = 0.f;
#pragma unroll
        for (int rg = 0; rg < 8; rg++) a += sm[OFF_BLOG + rg * CDIM + t];
        sm[OFF_USUM + t] = a;
    }
    __syncthreads();
    boundary(sm, &sm[OFF_USUM], 0, 1.f / 16.f, W, true, nullptr, wid, lane);
    __syncthreads();

    // ---------- 2 fused routing passes ----------
    for (int pass = 0; pass < 2; ++pass) {
        unsigned long long vac2[8][2];     // 8 capsules x 2 channel-pairs (4 channels)
#pragma unroll
        for (int m = 0; m < 8; m++) { vac2[m][0] = 0ull; vac2[m][1] = 0ull; }

        prefetch_chunk(sm, u, 0, 0, t);

        for (int chunk = 0; chunk < NCHUNK; ++chunk) {
            asm volatile("cp.async.wait_group 0;" ::: "memory");
            __syncthreads();
            if (chunk + 1 < NCHUNK) prefetch_chunk(sm, u, chunk + 1, (chunk + 1) & 1, t);
            const float* ub = &sm[OFF_U + (chunk & 1) * (CH * CDIM)];

            // --- step A: blog[n][row] partials, k-split 16 warps x 16 ch, 2 rows/lane ---
            {
                const int kg = wid;                 // channel group: 16 ch at kg*16
                const int r0 = lane, r1 = lane + 32;
                ulonglong2 uA[4], uB[4];
#pragma unroll
                for (int j = 0; j < 4; j++) {
                    uA[j] = *(const ulonglong2*)(ub + r0 * CDIM + (((kg * 4 + j) ^ (r0 & 15)) << 2));
                    uB[j] = *(const ulonglong2*)(ub + r1 * CDIM + (((kg * 4 + j) ^ (r1 & 15)) << 2));
                }
#pragma unroll
                for (int n = 0; n < NC; n++) {
                    const float* wb = &sm[OFF_W + n * CDIM + kg * 16];
                    unsigned long long a0 = 0ull, a1 = 0ull;
#pragma unroll
                    for (int j = 0; j < 4; j++) {
                        ulonglong2 w2 = *(const ulonglong2*)(wb + 4 * j);
                        a0 = ffma2(uA[j].x, w2.x, a0);
                        a0 = ffma2(uA[j].y, w2.y, a0);
                        a1 = ffma2(uB[j].x, w2.x, a1);
                        a1 = ffma2(uB[j].y, w2.y, a1);
                    }
                    float2 f0 = upk(a0), f1 = upk(a1);
                    sm[OFF_BLOG + kg * (NC * 65) + n * 65 + r0] = f0.x + f0.y;
                    sm[OFF_BLOG + kg * (NC * 65) + n * 65 + r1] = f1.x + f1.y;
                }
            }
            __syncthreads();

            // --- softmax over n (per row): reduce 16 k-partials, width-16 shuffles; 2 rows/thread ---
            {
                const int n = t & 15, ii0 = t >> 4;   // half-warp group = fixed ii
#pragma unroll
                for (int s2 = 0; s2 < 2; s2++) {
                    int ii = ii0 + s2 * 32;
                    float bl = 0.f;
#pragma unroll
                    for (int kg = 0; kg < 16; kg++)
                        bl += sm[OFF_BLOG + kg * (NC * 65) + n * 65 + ii];
                    float m = bl;
#pragma unroll
                    for (int o = 8; o > 0; o >>= 1) m = fmaxf(m, __shfl_xor_sync(0xffffffffu, m, o, 16));
                    float e = __expf(bl - m);
                    float ssum = e;
#pragma unroll
                    for (int o = 8; o > 0; o >>= 1) ssum += __shfl_xor_sync(0xffffffffu, ssum, o, 16);
                    sm[OFF_CS + ii * NC + n] = e / ssum;   // transposed [row][n]
                }
            }
            __syncthreads();

            // --- step C: v[n][c] += c[n][row] * u[row][c]; 8 n x 4 ch per thread, 16 rows ---
            {
                const float* csb = &sm[OFF_CS + c_nh * 8];
#pragma unroll 4
                for (int r16 = 0; r16 < 16; r16++) {
                    int row = c_rgrp * 16 + r16;
                    ulonglong2 uu = *(const ulonglong2*)(ub + row * CDIM + ((c_Q ^ (row & 15)) << 2));
                    float4 ca = *(const float4*)(csb + row * NC);       // c[nh*8+0..3][row]
                    float4 cb = *(const float4*)(csb + row * NC + 4);   // c[nh*8+4..7][row]
                    const float cv[8] = {ca.x, ca.y, ca.z, ca.w, cb.x, cb.y, cb.z, cb.w};
#pragma unroll
                    for (int m = 0; m < 8; m++) {
                        unsigned long long cc = pk2(cv[m]);
                        vac2[m][0] = ffma2(uu.x, cc, vac2[m][0]);
                        vac2[m][1] = ffma2(uu.y, cc, vac2[m][1]);
                    }
                }
            }
        }
        __syncthreads();   // U ring dead; VPART (alias) becomes live

        // dump register v partials (4 rgrp copies), reduce
        {
#pragma unroll
            for (int m = 0; m < 8; m++) {
                int n = c_nh * 8 + m;
                float* base = &sm[OFF_VPART + c_rgrp * (NC * CDIM) + n * CDIM + c_Q * 4];
                *(unsigned long long*)(base + 0) = vac2[m][0];
                *(unsigned long long*)(base + 2) = vac2[m][1];
            }
        }
        __syncthreads();
        for (int q = t; q < (NC * CDIM) / 4; q += THREADS) {
            float4 a = *(float4*)&sm[OFF_VPART + 4 * q];
            float4 b1 = *(float4*)&sm[OFF_VPART + 1 * NC * CDIM + 4 * q];
            float4 b2 = *(float4*)&sm[OFF_VPART + 2 * NC * CDIM + 4 * q];
            float4 b3 = *(float4*)&sm[OFF_VPART + 3 * NC * CDIM + 4 * q];
            a.x += b1.x + b2.x + b3.x;
            a.y += b1.y + b2.y + b3.y;
            a.z += b1.z + b2.z + b3.z;
            a.w += b1.w + b2.w + b3.w;
            *(float4*)&sm[OFF_VPART + 4 * q] = a;
        }
        __syncthreads();

        bool last = (pass == 1);
        boundary(sm, &sm[OFF_VPART], CDIM, 1.f, W, !last,
                 last ? (gout + (size_t)b * NC * DD) : nullptr, wid, lane);
        __syncthreads();   // protects next pass's prefetch into aliased U ring
    }
}

extern "C" void kernel_launch(void* const* d_in, const int* in_sizes, int n_in,
                              void* d_out, int out_size) {
    const float* u_vecs = (const float*)d_in[0];   // (128, 1024, 256) fp32
    const float* W      = (const float*)d_in[1];   // (256, 512) fp32
    float* out          = (float*)d_out;           // (128, 16, 32) fp32

    cudaFuncSetAttribute(caps_route_kernel, cudaFuncAttributeMaxDynamicSharedMemorySize, SMEM_BYTES);
    caps_route_kernel<<<128, THREADS, SMEM_BYTES>>>(u_vecs, W, out);
}